// round 4
// baseline (speedup 1.0000x reference)
#include <cuda_runtime.h>
#include <cstdint>
#include <cstddef>

// Problem dims
#define T_STEPS 512
#define BATCH   256
#define DIN     128
#define HDIM    256
#define PDIM    128
#define DH      384            // DIN + HDIM

// 32 clusters x 4 CTAs. Cluster owns 8 batch rows for all T.
// Rank r owns prototypes [r*32, r*32+32) and hidden cols [r*64, r*64+64) of all gates.
#define CLUSTER 4
#define BT      8
#define NTHR    512

// Shared-memory layout (offsets in floats)
#define OFF_PROTO 0                 // [32][384]
#define OFF_WT    12288             // [128][256]  WT[p][g*64+hl]
#define OFF_C     45056             // [8][384]    combined [x | h]
#define OFF_KT    48128             // [128][8]    kT[p][b]
#define OFF_PREP  49152             // [2][8][256] gate preact partials (p-halves)
#define OFF_PARTS 53248             // [2][32][8]  RBF dot partials (j-segments)
#define OFF_CX    53760             // [8][64]
#define OFF_BIAS  54272             // [256]
#define OFF_PN    54528             // [32]
#define OFF_CNX   54560             // [8]  x-part of ||c||^2
#define OFF_CNH   54568             // [8]  h-part of ||c||^2
#define SMEM_FLOATS 54576
#define SMEM_BYTES  (SMEM_FLOATS * 4)   // 218304 B

typedef unsigned long long ull;

// ---------------- helpers ----------------

__device__ __forceinline__ uint32_t cvta_shared_u32(const void* p) {
    uint32_t a;
    asm("{ .reg .u64 t; cvta.to.shared.u64 t, %1; cvt.u32.u64 %0, t; }"
        : "=r"(a) : "l"(p));
    return a;
}
__device__ __forceinline__ void stc_f32(uint32_t saddr, uint32_t rankv, float v) {
    uint32_t ra;
    asm volatile("mapa.shared::cluster.u32 %0, %1, %2;" : "=r"(ra) : "r"(saddr), "r"(rankv));
    asm volatile("st.shared::cluster.f32 [%0], %1;" :: "r"(ra), "f"(v) : "memory");
}
#define CARRIVE() asm volatile("barrier.cluster.arrive.aligned;" ::: "memory")
#define CWAIT()   asm volatile("barrier.cluster.wait.aligned;"   ::: "memory")

__device__ __forceinline__ ull pack2(float lo, float hi) {
    ull r; asm("mov.b64 %0, {%1, %2};" : "=l"(r) : "f"(lo), "f"(hi)); return r;
}
__device__ __forceinline__ ull ffma2(ull a, ull b, ull c) {
    ull d; asm("fma.rn.f32x2 %0, %1, %2, %3;" : "=l"(d) : "l"(a), "l"(b), "l"(c)); return d;
}
__device__ __forceinline__ ull addf2(ull a, ull b) {
    ull d; asm("add.rn.f32x2 %0, %1, %2;" : "=l"(d) : "l"(a), "l"(b)); return d;
}
__device__ __forceinline__ void unpack2(ull v, float& lo, float& hi) {
    asm("mov.b64 {%0, %1}, %2;" : "=f"(lo), "=f"(hi) : "l"(v));
}
__device__ __forceinline__ float sigf(float x) {
    return __fdividef(1.f, 1.f + __expf(-x));
}
__device__ __forceinline__ float tanhf_fast(float x) {
    float ax = fabsf(x);
    float e  = __expf(-2.f * ax);
    float r  = __fdividef(1.f - e, 1.f + e);
    return copysignf(r, x);
}

// one 32-f2 chunk of the RBF dot: warp (jseg=w>>3, 4 protos pp0=(w&7)*4),
// f2 index jj within the row
__device__ __forceinline__ void rbf_chunk(ull acc2[32], const float* cS,
                                          const float* protoS, int pp0, int jj) {
    ull cv2[8], pv2[4];
    #pragma unroll
    for (int b2 = 0; b2 < 8; b2++)
        cv2[b2] = ((const ull*)(cS + b2 * DH))[jj];
    #pragma unroll
    for (int q = 0; q < 4; q++)
        pv2[q] = ((const ull*)(protoS + (pp0 + q) * DH))[jj];
    #pragma unroll
    for (int b2 = 0; b2 < 8; b2++) {
        #pragma unroll
        for (int q = 0; q < 4; q++)
            acc2[b2 * 4 + q] = ffma2(cv2[b2], pv2[q], acc2[b2 * 4 + q]);
    }
}

// ---------------- kernel ----------------

__global__ void __cluster_dims__(CLUSTER, 1, 1) __launch_bounds__(NTHR, 1)
qlstm_kernel(const float* __restrict__ xin,   const float* __restrict__ proto,
             const float* __restrict__ Wf_p,  const float* __restrict__ bf_p,
             const float* __restrict__ Wi_p,  const float* __restrict__ bi_p,
             const float* __restrict__ Wg_p,  const float* __restrict__ bg_p,
             const float* __restrict__ Wo_p,  const float* __restrict__ bo_p,
             float* __restrict__ out)
{
    extern __shared__ float sm[];
    float* protoS = sm + OFF_PROTO;
    float* WTs    = sm + OFF_WT;
    float* cS     = sm + OFF_C;
    float* kTs    = sm + OFF_KT;
    float* preP   = sm + OFF_PREP;
    float* partS  = sm + OFF_PARTS;
    float* cxS    = sm + OFF_CX;
    float* biasS  = sm + OFF_BIAS;
    float* pnS    = sm + OFF_PN;
    float* cnxS   = sm + OFF_CNX;
    float* cnhS   = sm + OFF_CNH;

    const int tid  = threadIdx.x;
    const int lane = tid & 31;
    const int w    = tid >> 5;                  // warp 0..15
    const int rank = (int)(blockIdx.x & 3);
    const int B0   = (int)(blockIdx.x >> 2) * BT;
    const uint32_t smem_u32 = cvta_shared_u32(sm);

    const int jseg = w >> 3;                    // 0/1
    const int pp0  = (w & 7) * 4;               // warp's 4 local protos

    // ---------- one-time init ----------
    {
        const float* psrc = proto + (size_t)(rank * 32) * DH;
        for (int i = tid; i < 32 * DH; i += NTHR) protoS[i] = psrc[i];
    }
    {
        #pragma unroll
        for (int g = 0; g < 4; g++) {
            const float* Wg_ = (g == 0) ? Wf_p : (g == 1) ? Wi_p : (g == 2) ? Wg_p : Wo_p;
            for (int i = tid; i < PDIM * 64; i += NTHR) {
                int hl = i >> 7;
                int p  = i & 127;
                WTs[p * 256 + g * 64 + hl] = Wg_[(size_t)(rank * 64 + hl) * PDIM + p];
            }
        }
    }
    if (tid < 64) {
        biasS[        tid] = bf_p[rank * 64 + tid];
        biasS[ 64 +   tid] = bi_p[rank * 64 + tid];
        biasS[128 +   tid] = bg_p[rank * 64 + tid];
        biasS[192 +   tid] = bo_p[rank * 64 + tid];
    }
    for (int i = tid; i < BT * DH; i += NTHR) cS[i]  = 0.f;
    for (int i = tid; i < BT * 64; i += NTHR) cxS[i] = 0.f;
    if (tid < 8) cnhS[tid] = 0.f;
    __syncthreads();

    if (tid < 32) {
        const float4* pr = (const float4*)(protoS + tid * DH);
        float s = 0.f;
        #pragma unroll 8
        for (int q = 0; q < DH / 4; q++) {
            float4 v = pr[q];
            s += v.x * v.x + v.y * v.y + v.z * v.z + v.w * v.w;
        }
        pnS[tid] = s;
    }
    __syncthreads();
    CARRIVE(); CWAIT();     // all CTAs initialized before any DSMEM traffic

    ull acc2[32];

    // ---------- pre-loop pipeline for t = 0 ----------
    float2 xreg = ((const float2*)(xin + (size_t)B0 * DIN))[tid];          // x(0)
    ((float2*)(cS + (tid >> 6) * DH))[tid & 63] = xreg;
    xreg = ((const float2*)(xin + (size_t)BATCH * DIN + (size_t)B0 * DIN))[tid]; // x(1)
    __syncthreads();
    #pragma unroll
    for (int i = 0; i < 32; i++) acc2[i] = 0ull;
    rbf_chunk(acc2, cS, protoS, pp0, jseg * 32 + lane);     // x-part (j<128)
    if (w < 8) {                                            // cnx[b=w]
        float4 v = ((const float4*)(cS + w * DH))[lane];
        float s = v.x * v.x + v.y * v.y + v.z * v.z + v.w * v.w;
        #pragma unroll
        for (int m = 16; m >= 1; m >>= 1) s += __shfl_xor_sync(0xffffffffu, s, m);
        if (lane == 0) cnxS[w] = s;
    }
    CARRIVE();   // "h-exchange" arrive for t=0 (h is zero, nothing delivered)

    for (int t = 0; t < T_STEPS; t++) {
        CWAIT();   // h(t-1) from all ranks visible

        // cnh[b] (warps 8..15) — post-wait h-norm
        if (w >= 8) {
            const int b = w - 8;
            const float4* cb = (const float4*)(cS + b * DH);
            float4 a0 = cb[32 + lane];
            float4 a1 = cb[64 + lane];
            float s = a0.x * a0.x + a0.y * a0.y + a0.z * a0.z + a0.w * a0.w
                    + a1.x * a1.x + a1.y * a1.y + a1.z * a1.z + a1.w * a1.w;
            #pragma unroll
            for (int m = 16; m >= 1; m >>= 1) s += __shfl_xor_sync(0xffffffffu, s, m);
            if (lane == 0) cnhS[b] = s;
        }

        // ---------- phase B h-part: 2 chunks per warp ----------
        rbf_chunk(acc2, cS, protoS, pp0, 64 + jseg * 64 +      lane);
        rbf_chunk(acc2, cS, protoS, pp0, 64 + jseg * 64 + 32 + lane);

        // xor-merge reduce: lane l -> packed partial for (b=l>>2, q=l&3)
        #pragma unroll
        for (int s5 = 0; s5 < 5; s5++) {
            const int m = 1 << s5;
            const int L = 32 >> s5;
            const bool hi = (lane & m) != 0;
            #pragma unroll
            for (int i = 0; i < (L >> 1); i++) {
                ull mine = hi ? acc2[2 * i + 1] : acc2[2 * i];
                ull send = hi ? acc2[2 * i]     : acc2[2 * i + 1];
                acc2[i] = addf2(mine, __shfl_xor_sync(0xffffffffu, send, m));
            }
        }
        {
            float lo, hi_;
            unpack2(acc2[0], lo, hi_);
            const int b  = lane >> 2;
            const int pl = pp0 + (lane & 3);
            partS[jseg * 256 + pl * 8 + b] = lo + hi_;
        }
        __syncthreads();

        // ---------- kv + delivery (STS local, stc to peers) ----------
        {
            const int idx = tid >> 1;
            const int pl  = idx >> 3;
            const int b   = idx & 7;
            const float s  = partS[pl * 8 + b] + partS[256 + pl * 8 + b];
            const float d2 = cnxS[b] + cnhS[b] + pnS[pl] - 2.f * s;
            const float kv = __expf(-d2);            // GAMMA = 1
            const int   pg = rank * 32 + pl;
            const uint32_t a  = smem_u32 + (uint32_t)(OFF_KT + pg * 8 + b) * 4u;
            const int      r0 = (tid & 1) * 2;
            if (r0     == rank) kTs[pg * 8 + b] = kv; else stc_f32(a, (uint32_t)r0,     kv);
            if (r0 + 1 == rank) kTs[pg * 8 + b] = kv; else stc_f32(a, (uint32_t)(r0+1), kv);
        }
        CARRIVE();          // k-exchange arrive (release of peer stc stores)
        __syncthreads();    // local STS of own kT visible

        // ---------- phase C, own-p chunk (hidden behind k-barrier) ----------
        const int hc = tid & 255;
        const int ph = tid >> 8;
        ull a0, a1, a2, a3;
        {
            const float bv = ph ? 0.f : biasS[hc];
            a0 = pack2(bv, bv); a1 = a0; a2 = a0; a3 = a0;
        }
        const float* wcol = WTs + hc;
        {
            int p = rank * 32 + ph * 16;
            #pragma unroll 8
            for (int i = 0; i < 16; i++, p++) {
                const ulonglong2* kp = (const ulonglong2*)(kTs + p * 8);
                const ulonglong2 k01 = kp[0];
                const ulonglong2 k23 = kp[1];
                const ull wv2 = pack2(wcol[p * 256], wcol[p * 256]);
                a0 = ffma2(k01.x, wv2, a0);
                a1 = ffma2(k01.y, wv2, a1);
                a2 = ffma2(k23.x, wv2, a2);
                a3 = ffma2(k23.y, wv2, a3);
            }
        }
        CWAIT();            // full kT now visible

        // ---------- phase C, remaining 96 p ----------
        {
            const int base = rank * 32 + 32 + ph * 48;
            #pragma unroll 8
            for (int i = 0; i < 48; i++) {
                const int p = (base + i) & 127;
                const ulonglong2* kp = (const ulonglong2*)(kTs + p * 8);
                const ulonglong2 k01 = kp[0];
                const ulonglong2 k23 = kp[1];
                const ull wv2 = pack2(wcol[p * 256], wcol[p * 256]);
                a0 = ffma2(k01.x, wv2, a0);
                a1 = ffma2(k01.y, wv2, a1);
                a2 = ffma2(k23.x, wv2, a2);
                a3 = ffma2(k23.y, wv2, a3);
            }
        }
        {
            float lo, hi_;
            float* dst = preP + ph * 2048 + hc;
            unpack2(a0, lo, hi_); dst[0]    = lo; dst[256]  = hi_;
            unpack2(a1, lo, hi_); dst[512]  = lo; dst[768]  = hi_;
            unpack2(a2, lo, hi_); dst[1024] = lo; dst[1280] = hi_;
            unpack2(a3, lo, hi_); dst[1536] = lo; dst[1792] = hi_;
        }
        __syncthreads();

        // ---------- gates + state update + h delivery ----------
        float hval, cval;
        {
            const int b  = tid >> 6;
            const int hl = tid & 63;
            const float pf  = preP[b * 256 +       hl] + preP[2048 + b * 256 +       hl];
            const float pi_ = preP[b * 256 +  64 + hl] + preP[2048 + b * 256 +  64 + hl];
            const float pg_ = preP[b * 256 + 128 + hl] + preP[2048 + b * 256 + 128 + hl];
            const float po  = preP[b * 256 + 192 + hl] + preP[2048 + b * 256 + 192 + hl];
            const float f  = sigf(pf);
            const float ii = sigf(pi_);
            const float g  = tanhf_fast(pg_);
            const float oo = sigf(po);
            cval = f * cxS[b * 64 + hl] + ii * g;
            cxS[b * 64 + hl] = cval;
            hval = oo * tanhf_fast(cval);

            if (t + 1 < T_STEPS) {
                // own combined buffer (STS) + 3 peers (DSMEM)
                cS[b * DH + DIN + rank * 64 + hl] = hval;
                const uint32_t a = smem_u32
                    + (uint32_t)(OFF_C + b * DH + DIN + rank * 64 + hl) * 4u;
                #pragma unroll
                for (int r = 0; r < 4; r++)
                    if (r != rank) stc_f32(a, (uint32_t)r, hval);
                CARRIVE();   // h-exchange arrive (everything below overlaps it)
            }
        }

        // global stores (hidden behind the h-barrier)
        {
            const int b  = tid >> 6;
            const int hl = tid & 63;
            const size_t obase = (size_t)t * BATCH * HDIM
                               + (size_t)(B0 + b) * HDIM + rank * 64 + hl;
            out[obase] = hval;
            if (t == T_STEPS - 1) {
                const size_t fbase = (size_t)T_STEPS * BATCH * HDIM
                                   + (size_t)(B0 + b) * HDIM + rank * 64 + hl;
                out[fbase] = hval;                               // hx
                out[fbase + (size_t)BATCH * HDIM] = cval;        // cx
            }
        }

        if (t + 1 < T_STEPS) {
            // x(t+1) into cS, prefetch x(t+2), start next step's x-part dot
            ((float2*)(cS + (tid >> 6) * DH))[tid & 63] = xreg;
            if (t + 2 < T_STEPS) {
                xreg = ((const float2*)(xin + (size_t)(t + 2) * BATCH * DIN
                                            + (size_t)B0 * DIN))[tid];
            }
            __syncthreads();
            #pragma unroll
            for (int i = 0; i < 32; i++) acc2[i] = 0ull;
            rbf_chunk(acc2, cS, protoS, pp0, jseg * 32 + lane);
            if (w < 8) {
                float4 v = ((const float4*)(cS + w * DH))[lane];
                float s = v.x * v.x + v.y * v.y + v.z * v.z + v.w * v.w;
                #pragma unroll
                for (int m = 16; m >= 1; m >>= 1)
                    s += __shfl_xor_sync(0xffffffffu, s, m);
                if (lane == 0) cnxS[w] = s;
            }
        }
    }
}

extern "C" void kernel_launch(void* const* d_in, const int* in_sizes, int n_in,
                              void* d_out, int out_size) {
    (void)in_sizes; (void)n_in; (void)out_size;
    const float* xin   = (const float*)d_in[0];
    const float* proto = (const float*)d_in[1];
    const float* Wf    = (const float*)d_in[2];
    const float* bf    = (const float*)d_in[3];
    const float* Wi    = (const float*)d_in[4];
    const float* bi    = (const float*)d_in[5];
    const float* Wg    = (const float*)d_in[6];
    const float* bg    = (const float*)d_in[7];
    const float* Wo    = (const float*)d_in[8];
    const float* bo    = (const float*)d_in[9];
    float* out = (float*)d_out;

    cudaFuncSetAttribute(qlstm_kernel,
                         cudaFuncAttributeMaxDynamicSharedMemorySize, SMEM_BYTES);
    qlstm_kernel<<<(BATCH / BT) * CLUSTER, NTHR, SMEM_BYTES>>>(
        xin, proto, Wf, bf, Wi, bi, Wg, bg, Wo, bo, out);
}

// round 5
// speedup vs baseline: 1.0516x; 1.0516x over previous
#include <cuda_runtime.h>
#include <cstdint>
#include <cstddef>

// Problem dims
#define T_STEPS 512
#define BATCH   256
#define DIN     128
#define HDIM    256
#define PDIM    128
#define DH      384            // DIN + HDIM

// 32 clusters x 4 CTAs. Each cluster owns 8 batch rows for all T.
// Rank r owns prototypes [r*32, r*32+32) and hidden cols [r*64, r*64+64) of all gates.
#define CLUSTER 4
#define BT      8
#define NTHR    256

// Shared-memory layout (offsets in floats)
#define OFF_PROTO 0                 // [32][384]  rank's prototype slice
#define OFF_WT    12288             // [128][256] WT[p][g*64+hl] = W_g[rank*64+hl][p]
#define OFF_C     45056             // [8][384]   combined [x | h]
#define OFF_KT    48128             // [128][8]   kT[p][b] (full P, all ranks write)
#define OFF_PRE   49152             // [8][256]   gate preactivations (rank's cols)
#define OFF_CX    51200             // [8][64]    cell-state slice (rank-local)
#define OFF_BIAS  51712             // [256]
#define OFF_PN    51968             // [32]       ||proto_p||^2
#define OFF_CN    52000             // [8]        ||c_b||^2
#define SMEM_FLOATS 52008
#define SMEM_BYTES  (SMEM_FLOATS * 4)   // 208032 B

typedef unsigned long long ull;

// ---------------- helpers ----------------

__device__ __forceinline__ uint32_t cvta_shared_u32(const void* p) {
    uint32_t a;
    asm("{ .reg .u64 t; cvta.to.shared.u64 t, %1; cvt.u32.u64 %0, t; }"
        : "=r"(a) : "l"(p));
    return a;
}

__device__ __forceinline__ void stc_f32(uint32_t saddr, uint32_t rankv, float v) {
    uint32_t ra;
    asm volatile("mapa.shared::cluster.u32 %0, %1, %2;" : "=r"(ra) : "r"(saddr), "r"(rankv));
    asm volatile("st.shared::cluster.f32 [%0], %1;" :: "r"(ra), "f"(v) : "memory");
}

__device__ __forceinline__ void cluster_sync_() {
    asm volatile("barrier.cluster.arrive.aligned;" ::: "memory");
    asm volatile("barrier.cluster.wait.aligned;"   ::: "memory");
}

__device__ __forceinline__ ull pack2(float lo, float hi) {
    ull r; asm("mov.b64 %0, {%1, %2};" : "=l"(r) : "f"(lo), "f"(hi)); return r;
}
__device__ __forceinline__ ull ffma2(ull a, ull b, ull c) {
    ull d; asm("fma.rn.f32x2 %0, %1, %2, %3;" : "=l"(d) : "l"(a), "l"(b), "l"(c)); return d;
}
__device__ __forceinline__ void unpack2(ull v, float& lo, float& hi) {
    asm("mov.b64 {%0, %1}, %2;" : "=f"(lo), "=f"(hi) : "l"(v));
}

__device__ __forceinline__ float sigf(float x) {
    return __fdividef(1.f, 1.f + __expf(-x));
}
__device__ __forceinline__ float tanhf_fast(float x) {
    float ax = fabsf(x);
    float e  = __expf(-2.f * ax);
    float r  = __fdividef(1.f - e, 1.f + e);
    return copysignf(r, x);
}

// ---------------- kernel ----------------

__global__ void __cluster_dims__(CLUSTER, 1, 1) __launch_bounds__(NTHR, 1)
qlstm_kernel(const float* __restrict__ xin,   const float* __restrict__ proto,
             const float* __restrict__ Wf_p,  const float* __restrict__ bf_p,
             const float* __restrict__ Wi_p,  const float* __restrict__ bi_p,
             const float* __restrict__ Wg_p,  const float* __restrict__ bg_p,
             const float* __restrict__ Wo_p,  const float* __restrict__ bo_p,
             float* __restrict__ out)
{
    extern __shared__ float sm[];
    float* protoS = sm + OFF_PROTO;
    float* WTs    = sm + OFF_WT;
    float* cS     = sm + OFF_C;
    float* kTs    = sm + OFF_KT;
    float* preS   = sm + OFF_PRE;
    float* cxS    = sm + OFF_CX;
    float* biasS  = sm + OFF_BIAS;
    float* pnS    = sm + OFF_PN;
    float* cnS    = sm + OFF_CN;

    const int tid  = threadIdx.x;
    const int lane = tid & 31;
    const int w    = tid >> 5;                  // warp id 0..7
    const int rank = (int)(blockIdx.x & 3);
    const int B0   = (int)(blockIdx.x >> 2) * BT;
    const uint32_t smem_u32 = cvta_shared_u32(sm);

    // ---------- one-time init ----------
    {
        const float* psrc = proto + (size_t)(rank * 32) * DH;
        for (int i = tid; i < 32 * DH; i += NTHR) protoS[i] = psrc[i];
    }
    {
        #pragma unroll
        for (int g = 0; g < 4; g++) {
            const float* Wg_ = (g == 0) ? Wf_p : (g == 1) ? Wi_p : (g == 2) ? Wg_p : Wo_p;
            for (int i = tid; i < PDIM * 64; i += NTHR) {
                int hl = i >> 7;           // 0..63
                int p  = i & 127;          // coalesced over p
                WTs[p * 256 + g * 64 + hl] = Wg_[(size_t)(rank * 64 + hl) * PDIM + p];
            }
        }
    }
    if (tid < 64) {
        biasS[        tid] = bf_p[rank * 64 + tid];
        biasS[ 64 +   tid] = bi_p[rank * 64 + tid];
        biasS[128 +   tid] = bg_p[rank * 64 + tid];
        biasS[192 +   tid] = bo_p[rank * 64 + tid];
    }
    for (int i = tid; i < BT * DH; i += NTHR) cS[i]  = 0.f;
    for (int i = tid; i < BT * 64; i += NTHR) cxS[i] = 0.f;
    __syncthreads();

    if (tid < 32) {
        const float4* pr = (const float4*)(protoS + tid * DH);
        float s = 0.f;
        #pragma unroll 8
        for (int q = 0; q < DH / 4; q++) {
            float4 v = pr[q];
            s += v.x * v.x + v.y * v.y + v.z * v.z + v.w * v.w;
        }
        pnS[tid] = s;
    }
    __syncthreads();
    cluster_sync_();   // everyone initialized before DSMEM traffic

    // prefetch x for t=0: 8*128 floats = 256 float4
    float4 xreg = ((const float4*)(xin + (size_t)B0 * DIN))[tid];

    for (int t = 0; t < T_STEPS; t++) {
        // ---------- phase A: combined vector + ||c||^2 ----------
        ((float4*)(cS + (tid >> 5) * DH))[tid & 31] = xreg;
        if (t + 1 < T_STEPS) {
            xreg = ((const float4*)(xin + (size_t)(t + 1) * BATCH * DIN
                                        + (size_t)B0 * DIN))[tid];
        }
        __syncthreads();
        {
            // warp w computes cn[b=w]
            const float4* cb = (const float4*)(cS + w * DH);
            float4 a0 = cb[lane];
            float4 a1 = cb[32 + lane];
            float4 a2 = cb[64 + lane];
            float s = a0.x * a0.x + a0.y * a0.y + a0.z * a0.z + a0.w * a0.w
                    + a1.x * a1.x + a1.y * a1.y + a1.z * a1.z + a1.w * a1.w
                    + a2.x * a2.x + a2.y * a2.y + a2.z * a2.z + a2.w * a2.w;
            #pragma unroll
            for (int m = 16; m >= 1; m >>= 1)
                s += __shfl_xor_sync(0xffffffffu, s, m);
            if (lane == 0) cnS[w] = s;
        }
        __syncthreads();

        // ---------- phase B: RBF kernel, packed f32x2 ----------
        {
            const int pp0 = w * 4;          // warp owns 4 local protos
            ull acc2[32];
            #pragma unroll
            for (int i = 0; i < 32; i++) acc2[i] = 0ull;

            #pragma unroll 3
            for (int jc = 0; jc < 6; jc++) {
                const int jj = jc * 32 + lane;       // f2 index 0..191
                ull cv2[8], pv2[4];
                #pragma unroll
                for (int b2 = 0; b2 < 8; b2++)
                    cv2[b2] = ((const ull*)(cS + b2 * DH))[jj];
                #pragma unroll
                for (int q = 0; q < 4; q++)
                    pv2[q] = ((const ull*)(protoS + (pp0 + q) * DH))[jj];
                #pragma unroll
                for (int b2 = 0; b2 < 8; b2++) {
                    #pragma unroll
                    for (int q = 0; q < 4; q++)
                        acc2[b2 * 4 + q] = ffma2(cv2[b2], pv2[q], acc2[b2 * 4 + q]);
                }
            }
            // collapse packed halves (same dot), then scalar xor-merge
            float acc[32];
            #pragma unroll
            for (int i = 0; i < 32; i++) {
                float lo, hi;
                unpack2(acc2[i], lo, hi);
                acc[i] = lo + hi;
            }
            #pragma unroll
            for (int s5 = 0; s5 < 5; s5++) {
                const int m = 1 << s5;
                const int L = 32 >> s5;
                const bool hi = (lane & m) != 0;
                #pragma unroll
                for (int i = 0; i < (L >> 1); i++) {
                    float mine = hi ? acc[2 * i + 1] : acc[2 * i];
                    float send = hi ? acc[2 * i]     : acc[2 * i + 1];
                    acc[i] = mine + __shfl_xor_sync(0xffffffffu, send, m);
                }
            }
            const int b   = lane >> 2;
            const int ppl = lane & 3;
            const float d2 = cnS[b] + pnS[pp0 + ppl] - 2.f * acc[0];
            const float kv = __expf(-d2);     // GAMMA = 1
            const int  pg  = rank * 32 + pp0 + ppl;
            const uint32_t a = smem_u32 + (uint32_t)(OFF_KT + pg * 8 + b) * 4u;
            stc_f32(a, 0, kv); stc_f32(a, 1, kv); stc_f32(a, 2, kv); stc_f32(a, 3, kv);
        }
        cluster_sync_();   // full kT visible everywhere

        // ---------- phase C: gate GEMM (f32x2, direct 64-bit kT loads) ----------
        {
            const int hc = w * 32 + lane;     // rank-local gate column 0..255
            const float bv = biasS[hc];
            ull acc0 = pack2(bv, bv);
            ull acc1 = acc0, acc2_ = acc0, acc3 = acc0;
            const float* wcol = WTs + hc;

            #pragma unroll 4
            for (int p = 0; p < PDIM; p++) {
                const ulonglong2* kp = (const ulonglong2*)(kTs + p * 8);
                const ulonglong2 k01 = kp[0];     // (b0,b1),(b2,b3)
                const ulonglong2 k23 = kp[1];     // (b4,b5),(b6,b7)
                const float wv = wcol[p * 256];
                const ull wv2 = pack2(wv, wv);
                acc0  = ffma2(k01.x, wv2, acc0);
                acc1  = ffma2(k01.y, wv2, acc1);
                acc2_ = ffma2(k23.x, wv2, acc2_);
                acc3  = ffma2(k23.y, wv2, acc3);
            }
            float lo, hi;
            unpack2(acc0,  lo, hi); preS[0 * 256 + hc] = lo; preS[1 * 256 + hc] = hi;
            unpack2(acc1,  lo, hi); preS[2 * 256 + hc] = lo; preS[3 * 256 + hc] = hi;
            unpack2(acc2_, lo, hi); preS[4 * 256 + hc] = lo; preS[5 * 256 + hc] = hi;
            unpack2(acc3,  lo, hi); preS[6 * 256 + hc] = lo; preS[7 * 256 + hc] = hi;
        }
        __syncthreads();

        // ---------- gate combine + state update + outputs ----------
        #pragma unroll
        for (int u = 0; u < 2; u++) {
            const int idx = tid + u * NTHR;     // 512 (b,hl) pairs over 256 threads
            const int b  = idx >> 6;
            const int hl = idx & 63;
            const float pf  = preS[b * 256 +       hl];
            const float pi_ = preS[b * 256 +  64 + hl];
            const float pg_ = preS[b * 256 + 128 + hl];
            const float po  = preS[b * 256 + 192 + hl];
            const float f  = sigf(pf);
            const float ii = sigf(pi_);
            const float g  = tanhf_fast(pg_);
            const float oo = sigf(po);
            const float cv = f * cxS[b * 64 + hl] + ii * g;
            cxS[b * 64 + hl] = cv;
            const float h = oo * tanhf_fast(cv);

            const size_t obase = (size_t)t * BATCH * HDIM
                               + (size_t)(B0 + b) * HDIM + rank * 64 + hl;
            out[obase] = h;

            // deliver h slice into every rank's combined buffer for next step
            const uint32_t a = smem_u32
                + (uint32_t)(OFF_C + b * DH + DIN + rank * 64 + hl) * 4u;
            stc_f32(a, 0, h); stc_f32(a, 1, h); stc_f32(a, 2, h); stc_f32(a, 3, h);

            if (t == T_STEPS - 1) {
                const size_t fbase = (size_t)T_STEPS * BATCH * HDIM
                                   + (size_t)(B0 + b) * HDIM + rank * 64 + hl;
                out[fbase] = h;                                  // hx
                out[fbase + (size_t)BATCH * HDIM] = cv;          // cx
            }
        }
        cluster_sync_();   // h deliveries complete before next step's reads
    }
}

extern "C" void kernel_launch(void* const* d_in, const int* in_sizes, int n_in,
                              void* d_out, int out_size) {
    (void)in_sizes; (void)n_in; (void)out_size;
    const float* xin   = (const float*)d_in[0];
    const float* proto = (const float*)d_in[1];
    const float* Wf    = (const float*)d_in[2];
    const float* bf    = (const float*)d_in[3];
    const float* Wi    = (const float*)d_in[4];
    const float* bi    = (const float*)d_in[5];
    const float* Wg    = (const float*)d_in[6];
    const float* bg    = (const float*)d_in[7];
    const float* Wo    = (const float*)d_in[8];
    const float* bo    = (const float*)d_in[9];
    float* out = (float*)d_out;

    cudaFuncSetAttribute(qlstm_kernel,
                         cudaFuncAttributeMaxDynamicSharedMemorySize, SMEM_BYTES);
    qlstm_kernel<<<(BATCH / BT) * CLUSTER, NTHR, SMEM_BYTES>>>(
        xin, proto, Wf, bf, Wi, bi, Wg, bg, Wo, bo, out);
}

// round 7
// speedup vs baseline: 1.1009x; 1.0469x over previous
#include <cuda_runtime.h>
#include <cstdint>
#include <cstddef>

// Problem dims
#define T_STEPS 512
#define BATCH   256
#define DIN     128
#define HDIM    256
#define PDIM    128
#define DH      384            // DIN + HDIM

// 32 clusters x 4 CTAs. Each cluster owns 8 batch rows for all T.
// Rank r owns prototypes [r*32, r*32+32) and hidden cols [r*64, r*64+64) of all gates.
#define CLUSTER 4
#define BT      8
#define NTHR    256

// Shared-memory layout (offsets in floats)
#define OFF_PROTO 0                 // [32][384]  rank's prototype slice
#define OFF_WT    12288             // [128][256] WT[i][g*64+hl], row i <-> p=(rank*32+i)&127
#define OFF_C     45056             // [8][384]   combined [x | h]
#define OFF_KT    48128             // [128][8]   kT[i][b], row i <-> p=(rank*32+i)&127
#define OFF_PRE   49152             // [8][256]   gate preactivations (rank's cols)
#define OFF_CX    51200             // [8][64]    cell-state slice (rank-local)
#define OFF_BIAS  51712             // [256]
#define OFF_PN    51968             // [32]       ||proto_p||^2
#define OFF_CN    52000             // [8]        ||c_b||^2
#define OFF_KBAR  52008             // u64 mbarrier (k exchange)
#define OFF_HBAR  52010             // u64 mbarrier (h exchange)
#define SMEM_FLOATS 52012
#define SMEM_BYTES  (SMEM_FLOATS * 4)   // 208048 B

typedef unsigned long long ull;

// ---------------- helpers ----------------

__device__ __forceinline__ uint32_t cvta_shared_u32(const void* p) {
    uint32_t a;
    asm("{ .reg .u64 t; cvta.to.shared.u64 t, %1; cvt.u32.u64 %0, t; }"
        : "=r"(a) : "l"(p));
    return a;
}

__device__ __forceinline__ void stc_f32(uint32_t saddr, uint32_t rankv, float v) {
    uint32_t ra;
    asm volatile("mapa.shared::cluster.u32 %0, %1, %2;" : "=r"(ra) : "r"(saddr), "r"(rankv));
    asm volatile("st.shared::cluster.f32 [%0], %1;" :: "r"(ra), "f"(v) : "memory");
}

// arrive (release, cluster scope) on CTA `rankv`'s mbarrier at local offset saddr
__device__ __forceinline__ void mbar_arrive_remote(uint32_t saddr, uint32_t rankv) {
    uint32_t ra;
    asm volatile("mapa.shared::cluster.u32 %0, %1, %2;" : "=r"(ra) : "r"(saddr), "r"(rankv));
    asm volatile("mbarrier.arrive.release.cluster.shared::cluster.b64 _, [%0];"
                 :: "r"(ra) : "memory");
}

// wait on local mbarrier with acquire-cluster semantics
__device__ __forceinline__ void mbar_wait(uint32_t saddr, uint32_t phase) {
    uint32_t done;
    do {
        asm volatile(
            "{\n\t.reg .pred p;\n\t"
            "mbarrier.try_wait.parity.acquire.cluster.shared::cta.b64 p, [%1], %2, 0x989680;\n\t"
            "selp.b32 %0, 1, 0, p;\n\t}"
            : "=r"(done) : "r"(saddr), "r"(phase) : "memory");
    } while (!done);
}

__device__ __forceinline__ ull pack2(float lo, float hi) {
    ull r; asm("mov.b64 %0, {%1, %2};" : "=l"(r) : "f"(lo), "f"(hi)); return r;
}
__device__ __forceinline__ ull ffma2(ull a, ull b, ull c) {
    ull d; asm("fma.rn.f32x2 %0, %1, %2, %3;" : "=l"(d) : "l"(a), "l"(b), "l"(c)); return d;
}
__device__ __forceinline__ void unpack2(ull v, float& lo, float& hi) {
    asm("mov.b64 {%0, %1}, %2;" : "=f"(lo), "=f"(hi) : "l"(v));
}

__device__ __forceinline__ float sigf(float x) {
    return __fdividef(1.f, 1.f + __expf(-x));
}
__device__ __forceinline__ float tanhf_fast(float x) {
    float ax = fabsf(x);
    float e  = __expf(-2.f * ax);
    float r  = __fdividef(1.f - e, 1.f + e);
    return copysignf(r, x);
}

// ---------------- kernel ----------------

__global__ void __cluster_dims__(CLUSTER, 1, 1) __launch_bounds__(NTHR, 1)
qlstm_kernel(const float* __restrict__ xin,   const float* __restrict__ proto,
             const float* __restrict__ Wf_p,  const float* __restrict__ bf_p,
             const float* __restrict__ Wi_p,  const float* __restrict__ bi_p,
             const float* __restrict__ Wg_p,  const float* __restrict__ bg_p,
             const float* __restrict__ Wo_p,  const float* __restrict__ bo_p,
             float* __restrict__ out)
{
    extern __shared__ float sm[];
    float* protoS = sm + OFF_PROTO;
    float* WTs    = sm + OFF_WT;
    float* cS     = sm + OFF_C;
    float* kTs    = sm + OFF_KT;
    float* preS   = sm + OFF_PRE;
    float* cxS    = sm + OFF_CX;
    float* biasS  = sm + OFF_BIAS;
    float* pnS    = sm + OFF_PN;
    float* cnS    = sm + OFF_CN;

    const int tid  = threadIdx.x;
    const int lane = tid & 31;
    const int w    = tid >> 5;                  // warp id 0..7
    const int rank = (int)(blockIdx.x & 3);
    const int B0   = (int)(blockIdx.x >> 2) * BT;
    const uint32_t smem_u32 = cvta_shared_u32(sm);
    const uint32_t kbar = smem_u32 + OFF_KBAR * 4u;
    const uint32_t hbar = smem_u32 + OFF_HBAR * 4u;

    // ---------- one-time init ----------
    {
        const float* psrc = proto + (size_t)(rank * 32) * DH;
        for (int i = tid; i < 32 * DH; i += NTHR) protoS[i] = psrc[i];
    }
    {
        // WT row i holds W columns for p = (rank*32 + i) & 127  (rotated layout)
        #pragma unroll
        for (int g = 0; g < 4; g++) {
            const float* Wg_ = (g == 0) ? Wf_p : (g == 1) ? Wi_p : (g == 2) ? Wg_p : Wo_p;
            for (int idx = tid; idx < PDIM * 64; idx += NTHR) {
                int hl = idx >> 7;          // 0..63
                int i  = idx & 127;         // rotated row
                int p  = (rank * 32 + i) & 127;
                WTs[i * 256 + g * 64 + hl] = Wg_[(size_t)(rank * 64 + hl) * PDIM + p];
            }
        }
    }
    if (tid < 64) {
        biasS[        tid] = bf_p[rank * 64 + tid];
        biasS[ 64 +   tid] = bi_p[rank * 64 + tid];
        biasS[128 +   tid] = bg_p[rank * 64 + tid];
        biasS[192 +   tid] = bo_p[rank * 64 + tid];
    }
    for (int i = tid; i < BT * DH; i += NTHR) cS[i]  = 0.f;
    for (int i = tid; i < BT * 64; i += NTHR) cxS[i] = 0.f;
    if (tid == 0) {
        asm volatile("mbarrier.init.shared.b64 [%0], %1;" :: "r"(kbar), "r"(4u) : "memory");
        asm volatile("mbarrier.init.shared.b64 [%0], %1;" :: "r"(hbar), "r"(4u) : "memory");
    }
    __syncthreads();

    if (tid < 32) {
        const float4* pr = (const float4*)(protoS + tid * DH);
        float s = 0.f;
        #pragma unroll 8
        for (int q = 0; q < DH / 4; q++) {
            float4 v = pr[q];
            s += v.x * v.x + v.y * v.y + v.z * v.z + v.w * v.w;
        }
        pnS[tid] = s;
    }
    __syncthreads();
    // full HW cluster barrier once: mbarrier inits visible before any arrivals
    asm volatile("barrier.cluster.arrive.aligned;" ::: "memory");
    asm volatile("barrier.cluster.wait.aligned;"   ::: "memory");

    // pre-arm hbar so the t=0 wait passes (h(−1)=0 already in cS)
    if (tid < 4) mbar_arrive_remote(hbar, (uint32_t)tid);
    uint32_t phik = 0, phih = 0;

    // prefetch x for t=0: 8*128 floats = 256 float4
    float4 xreg = ((const float4*)(xin + (size_t)B0 * DIN))[tid];

    for (int t = 0; t < T_STEPS; t++) {
        // ---------- phase A: x into combined buffer, wait h, ||c||^2 ----------
        ((float4*)(cS + (tid >> 5) * DH))[tid & 31] = xreg;
        if (t + 1 < T_STEPS) {
            xreg = ((const float4*)(xin + (size_t)(t + 1) * BATCH * DIN
                                        + (size_t)B0 * DIN))[tid];
        }
        mbar_wait(hbar, phih);      // h(t-1) from all ranks visible
        phih ^= 1;
        __syncthreads();            // x part visible CTA-wide
        {
            // warp w computes cn[b=w]
            const float4* cb = (const float4*)(cS + w * DH);
            float4 a0 = cb[lane];
            float4 a1 = cb[32 + lane];
            float4 a2 = cb[64 + lane];
            float s = a0.x * a0.x + a0.y * a0.y + a0.z * a0.z + a0.w * a0.w
                    + a1.x * a1.x + a1.y * a1.y + a1.z * a1.z + a1.w * a1.w
                    + a2.x * a2.x + a2.y * a2.y + a2.z * a2.z + a2.w * a2.w;
            #pragma unroll
            for (int m = 16; m >= 1; m >>= 1)
                s += __shfl_xor_sync(0xffffffffu, s, m);
            if (lane == 0) cnS[w] = s;
        }
        __syncthreads();

        // ---------- phase B: RBF kernel, packed f32x2 ----------
        {
            const int pp0 = w * 4;          // warp owns 4 local protos
            ull acc2[32];
            #pragma unroll
            for (int i = 0; i < 32; i++) acc2[i] = 0ull;

            #pragma unroll 3
            for (int jc = 0; jc < 6; jc++) {
                const int jj = jc * 32 + lane;       // f2 index 0..191
                ull cv2[8], pv2[4];
                #pragma unroll
                for (int b2 = 0; b2 < 8; b2++)
                    cv2[b2] = ((const ull*)(cS + b2 * DH))[jj];
                #pragma unroll
                for (int q = 0; q < 4; q++)
                    pv2[q] = ((const ull*)(protoS + (pp0 + q) * DH))[jj];
                #pragma unroll
                for (int b2 = 0; b2 < 8; b2++) {
                    #pragma unroll
                    for (int q = 0; q < 4; q++)
                        acc2[b2 * 4 + q] = ffma2(cv2[b2], pv2[q], acc2[b2 * 4 + q]);
                }
            }
            float acc[32];
            #pragma unroll
            for (int i = 0; i < 32; i++) {
                float lo, hi;
                unpack2(acc2[i], lo, hi);
                acc[i] = lo + hi;
            }
            #pragma unroll
            for (int s5 = 0; s5 < 5; s5++) {
                const int m = 1 << s5;
                const int L = 32 >> s5;
                const bool hi = (lane & m) != 0;
                #pragma unroll
                for (int i = 0; i < (L >> 1); i++) {
                    float mine = hi ? acc[2 * i + 1] : acc[2 * i];
                    float send = hi ? acc[2 * i]     : acc[2 * i + 1];
                    acc[i] = mine + __shfl_xor_sync(0xffffffffu, send, m);
                }
            }
            const int b  = lane >> 2;
            const int lp = pp0 + (lane & 3);         // local proto index 0..31
            const float d2 = cnS[b] + pnS[lp] - 2.f * acc[0];
            const float kv = __expf(-d2);            // GAMMA = 1
            // own slot (rotated layout: own protos land at rows [0,32))
            kTs[lp * 8 + b] = kv;
            // peers: rank's protos land at row ((rank-rho)&3)*32 + lp in rho's buffer
            #pragma unroll
            for (int d = 1; d < 4; d++) {
                const int rho  = (rank + d) & 3;
                const int slot = (4 - d) * 32 + lp;
                stc_f32(smem_u32 + (uint32_t)(OFF_KT + slot * 8 + b) * 4u,
                        (uint32_t)rho, kv);
            }
        }
        __syncthreads();                       // own-kT STS + all stc issued
        if (tid < 4) mbar_arrive_remote(kbar, (uint32_t)tid);

        // ---------- phase C part 1: own 32 rows (overlaps k-exchange) ----------
        const int hc = w * 32 + lane;          // rank-local gate column 0..255
        ull acc0, acc1, acc2_, acc3;
        {
            const float bv = biasS[hc];
            acc0 = pack2(bv, bv); acc1 = acc0; acc2_ = acc0; acc3 = acc0;
        }
        const float* wcol = WTs + hc;
        #pragma unroll 4
        for (int i = 0; i < 32; i++) {
            const ulonglong2* kp = (const ulonglong2*)(kTs + i * 8);
            const ulonglong2 k01 = kp[0];
            const ulonglong2 k23 = kp[1];
            const float wv = wcol[i * 256];
            const ull wv2 = pack2(wv, wv);
            acc0  = ffma2(k01.x, wv2, acc0);
            acc1  = ffma2(k01.y, wv2, acc1);
            acc2_ = ffma2(k23.x, wv2, acc2_);
            acc3  = ffma2(k23.y, wv2, acc3);
        }
        mbar_wait(kbar, phik);                 // peer kT rows now visible
        phik ^= 1;

        // ---------- phase C part 2: remaining 96 rows ----------
        #pragma unroll 4
        for (int i = 32; i < 128; i++) {
            const ulonglong2* kp = (const ulonglong2*)(kTs + i * 8);
            const ulonglong2 k01 = kp[0];
            const ulonglong2 k23 = kp[1];
            const float wv = wcol[i * 256];
            const ull wv2 = pack2(wv, wv);
            acc0  = ffma2(k01.x, wv2, acc0);
            acc1  = ffma2(k01.y, wv2, acc1);
            acc2_ = ffma2(k23.x, wv2, acc2_);
            acc3  = ffma2(k23.y, wv2, acc3);
        }
        {
            float lo, hi;
            unpack2(acc0,  lo, hi); preS[0 * 256 + hc] = lo; preS[1 * 256 + hc] = hi;
            unpack2(acc1,  lo, hi); preS[2 * 256 + hc] = lo; preS[3 * 256 + hc] = hi;
            unpack2(acc2_, lo, hi); preS[4 * 256 + hc] = lo; preS[5 * 256 + hc] = hi;
            unpack2(acc3,  lo, hi); preS[6 * 256 + hc] = lo; preS[7 * 256 + hc] = hi;
        }
        __syncthreads();

        // ---------- gates + state update + h delivery ----------
        const bool deliver = (t + 1 < T_STEPS);
        float hv0, cv0, hv1, cv1;
        #pragma unroll
        for (int u = 0; u < 2; u++) {
            const int idx = tid + u * NTHR;     // 512 (b,hl) pairs
            const int b  = idx >> 6;
            const int hl = idx & 63;
            const float pf  = preS[b * 256 +       hl];
            const float pi_ = preS[b * 256 +  64 + hl];
            const float pg_ = preS[b * 256 + 128 + hl];
            const float po  = preS[b * 256 + 192 + hl];
            const float f  = sigf(pf);
            const float ii = sigf(pi_);
            const float g  = tanhf_fast(pg_);
            const float oo = sigf(po);
            const float cv = f * cxS[b * 64 + hl] + ii * g;
            cxS[b * 64 + hl] = cv;
            const float h = oo * tanhf_fast(cv);
            if (u == 0) { hv0 = h; cv0 = cv; } else { hv1 = h; cv1 = cv; }

            if (deliver) {
                // own combined buffer + 3 peers
                cS[b * DH + DIN + rank * 64 + hl] = h;
                const uint32_t a = smem_u32
                    + (uint32_t)(OFF_C + b * DH + DIN + rank * 64 + hl) * 4u;
                #pragma unroll
                for (int d = 1; d < 4; d++)
                    stc_f32(a, (uint32_t)((rank + d) & 3), h);
            }
        }
        if (deliver) {
            __syncthreads();
            if (tid < 4) mbar_arrive_remote(hbar, (uint32_t)tid);
        }

        // global stores overlap the h-exchange propagation
        #pragma unroll
        for (int u = 0; u < 2; u++) {
            const int idx = tid + u * NTHR;
            const int b  = idx >> 6;
            const int hl = idx & 63;
            const float h  = (u == 0) ? hv0 : hv1;
            const float cv = (u == 0) ? cv0 : cv1;
            const size_t obase = (size_t)t * BATCH * HDIM
                               + (size_t)(B0 + b) * HDIM + rank * 64 + hl;
            out[obase] = h;
            if (t == T_STEPS - 1) {
                const size_t fbase = (size_t)T_STEPS * BATCH * HDIM
                                   + (size_t)(B0 + b) * HDIM + rank * 64 + hl;
                out[fbase] = h;                                  // hx
                out[fbase + (size_t)BATCH * HDIM] = cv;          // cx
            }
        }
    }

    // terminal cluster barrier: no CTA may exit while peers might still have
    // st.shared::cluster / remote mbarrier traffic targeting its SMEM
    asm volatile("barrier.cluster.arrive.aligned;" ::: "memory");
    asm volatile("barrier.cluster.wait.aligned;"   ::: "memory");
}

extern "C" void kernel_launch(void* const* d_in, const int* in_sizes, int n_in,
                              void* d_out, int out_size) {
    (void)in_sizes; (void)n_in; (void)out_size;
    const float* xin   = (const float*)d_in[0];
    const float* proto = (const float*)d_in[1];
    const float* Wf    = (const float*)d_in[2];
    const float* bf    = (const float*)d_in[3];
    const float* Wi    = (const float*)d_in[4];
    const float* bi    = (const float*)d_in[5];
    const float* Wg    = (const float*)d_in[6];
    const float* bg    = (const float*)d_in[7];
    const float* Wo    = (const float*)d_in[8];
    const float* bo    = (const float*)d_in[9];
    float* out = (float*)d_out;

    cudaFuncSetAttribute(qlstm_kernel,
                         cudaFuncAttributeMaxDynamicSharedMemorySize, SMEM_BYTES);
    qlstm_kernel<<<(BATCH / BT) * CLUSTER, NTHR, SMEM_BYTES>>>(
        xin, proto, Wf, bf, Wi, bi, Wg, bg, Wo, bo, out);
}